// round 1
// baseline (speedup 1.0000x reference)
#include <cuda_runtime.h>
#include <cuda_bf16.h>
#include <math_constants.h>

// ---------------- shapes ----------------
// B=16, A=5 -> N = 80 folded batch
// x: [80, 4, 45,45,45]
// conv0: 4->32 k5 p1 : 45 -> 43 -> pool 21
// conv1: 32->32 k5 p1: 21 -> 19 -> pool 9
// conv2: 32->64 k4 p1: 9  -> 8  -> pool 4
// conv3: 64->64 k3 p0: 4  -> 2          -> feat [80,512]
// fc1: 1024->256, fc2: 512->128, fc3: 256->6 (per-agent, with mean-comm concat)

#define NN 80

__device__ float g_buf0[80u * 32u * 21u * 21u * 21u];   // 94.8 MB
__device__ float g_buf1[80u * 32u * 9u * 9u * 9u];
__device__ float g_buf2[80u * 64u * 4u * 4u * 4u];
__device__ float g_feat[80u * 512u];
__device__ float g_mean1[16u * 512u];
__device__ float g_fc1[80u * 256u];
__device__ float g_mean2[16u * 256u];
__device__ float g_fc2[80u * 128u];
__device__ float g_mean3[16u * 128u];

// ---------------- conv0: 4->32, k5, pad1, fused pool2 ----------------
// grid (21, 32, 80), block (21, 21)
__global__ void conv0_kernel(const float* __restrict__ x,
                             const float* __restrict__ w,
                             const float* __restrict__ bias,
                             const float* __restrict__ prelu,
                             float* __restrict__ out) {
    const int pz = blockIdx.x, c = blockIdx.y, n = blockIdx.z;
    const int px = threadIdx.x, py = threadIdx.y;
    __shared__ float ws[4 * 125];
    __shared__ float sb, sa;
    const int tid = py * 21 + px;
    for (int i = tid; i < 500; i += 441) ws[i] = w[c * 500 + i] * (1.0f / 255.0f);
    if (tid == 0) { sb = bias[c]; sa = prelu[0]; }
    __syncthreads();

    float acc[2][2][2] = {};
    for (int ic = 0; ic < 4; ic++) {
        const float* xp = x + ((size_t)(n * 4 + ic)) * (45 * 45 * 45);
        for (int zin = 0; zin < 6; zin++) {
            const int z = 2 * pz - 1 + zin;
            if ((unsigned)z >= 45u) continue;
#pragma unroll
            for (int yin = 0; yin < 6; yin++) {
                const int y = 2 * py - 1 + yin;
                if ((unsigned)y >= 45u) continue;
                const float* row = xp + ((size_t)z * 45 + y) * 45;
                float in[6];
#pragma unroll
                for (int xi = 0; xi < 6; xi++) {
                    const int xx = 2 * px - 1 + xi;
                    in[xi] = ((unsigned)xx < 45u) ? __ldg(row + xx) : 0.0f;
                }
#pragma unroll
                for (int oz = 0; oz < 2; oz++) {
                    const int kz = zin - oz;
                    if (kz < 0 || kz > 4) continue;
#pragma unroll
                    for (int oy = 0; oy < 2; oy++) {
                        const int ky = yin - oy;
                        if (ky < 0 || ky > 4) continue;
                        const float* wr = ws + ((ic * 5 + kz) * 5 + ky) * 5;
#pragma unroll
                        for (int kx = 0; kx < 5; kx++) {
                            const float wv = wr[kx];
                            acc[oz][oy][0] = fmaf(wv, in[kx], acc[oz][oy][0]);
                            acc[oz][oy][1] = fmaf(wv, in[kx + 1], acc[oz][oy][1]);
                        }
                    }
                }
            }
        }
    }
    float m = -CUDART_INF_F;
#pragma unroll
    for (int oz = 0; oz < 2; oz++)
#pragma unroll
        for (int oy = 0; oy < 2; oy++)
#pragma unroll
            for (int ox = 0; ox < 2; ox++)
                m = fmaxf(m, acc[oz][oy][ox] + sb);
    const float v = (m >= 0.0f) ? m : sa * m;
    out[(((size_t)(n * 32 + c) * 21 + pz) * 21 + py) * 21 + px] = v;
}

// ---------------- conv1: 32->32, k5, pad1, fused pool2 ----------------
// grid (3, 32, 80), block (9, 9, 3)
__global__ void conv1_kernel(const float* __restrict__ x,
                             const float* __restrict__ w,
                             const float* __restrict__ bias,
                             const float* __restrict__ prelu,
                             float* __restrict__ out) {
    const int c = blockIdx.y, n = blockIdx.z;
    const int px = threadIdx.x, py = threadIdx.y;
    const int pz = blockIdx.x * 3 + threadIdx.z;
    __shared__ float ws[32 * 125];
    __shared__ float sb, sa;
    const int tid = (threadIdx.z * 9 + py) * 9 + px;
    for (int i = tid; i < 4000; i += 243) ws[i] = w[c * 4000 + i];
    if (tid == 0) { sb = bias[c]; sa = prelu[0]; }
    __syncthreads();

    float acc[2][2][2] = {};
    for (int ic = 0; ic < 32; ic++) {
        const float* xp = x + ((size_t)(n * 32 + ic)) * (21 * 21 * 21);
        const float* wc = ws + ic * 125;
        for (int zin = 0; zin < 6; zin++) {
            const int z = 2 * pz - 1 + zin;
            if ((unsigned)z >= 21u) continue;
#pragma unroll
            for (int yin = 0; yin < 6; yin++) {
                const int y = 2 * py - 1 + yin;
                if ((unsigned)y >= 21u) continue;
                const float* row = xp + ((size_t)z * 21 + y) * 21;
                float in[6];
#pragma unroll
                for (int xi = 0; xi < 6; xi++) {
                    const int xx = 2 * px - 1 + xi;
                    in[xi] = ((unsigned)xx < 21u) ? __ldg(row + xx) : 0.0f;
                }
#pragma unroll
                for (int oz = 0; oz < 2; oz++) {
                    const int kz = zin - oz;
                    if (kz < 0 || kz > 4) continue;
#pragma unroll
                    for (int oy = 0; oy < 2; oy++) {
                        const int ky = yin - oy;
                        if (ky < 0 || ky > 4) continue;
                        const float* wr = wc + (kz * 5 + ky) * 5;
#pragma unroll
                        for (int kx = 0; kx < 5; kx++) {
                            const float wv = wr[kx];
                            acc[oz][oy][0] = fmaf(wv, in[kx], acc[oz][oy][0]);
                            acc[oz][oy][1] = fmaf(wv, in[kx + 1], acc[oz][oy][1]);
                        }
                    }
                }
            }
        }
    }
    float m = -CUDART_INF_F;
#pragma unroll
    for (int oz = 0; oz < 2; oz++)
#pragma unroll
        for (int oy = 0; oy < 2; oy++)
#pragma unroll
            for (int ox = 0; ox < 2; ox++)
                m = fmaxf(m, acc[oz][oy][ox] + sb);
    const float v = (m >= 0.0f) ? m : sa * m;
    out[(((size_t)(n * 32 + c) * 9 + pz) * 9 + py) * 9 + px] = v;
}

// ---------------- conv2: 32->64, k4, pad1, fused pool2 ----------------
// grid (64, 80), block (4, 4, 4)
__global__ void conv2_kernel(const float* __restrict__ x,
                             const float* __restrict__ w,
                             const float* __restrict__ bias,
                             const float* __restrict__ prelu,
                             float* __restrict__ out) {
    const int c = blockIdx.x, n = blockIdx.y;
    const int px = threadIdx.x, py = threadIdx.y, pz = threadIdx.z;
    __shared__ float ws[32 * 64];
    __shared__ float sb, sa;
    const int tid = (pz * 4 + py) * 4 + px;
    for (int i = tid; i < 2048; i += 64) ws[i] = w[c * 2048 + i];
    if (tid == 0) { sb = bias[c]; sa = prelu[0]; }
    __syncthreads();

    float acc[2][2][2] = {};
    for (int ic = 0; ic < 32; ic++) {
        const float* xp = x + ((size_t)(n * 32 + ic)) * (9 * 9 * 9);
        const float* wc = ws + ic * 64;
#pragma unroll
        for (int zin = 0; zin < 5; zin++) {
            const int z = 2 * pz - 1 + zin;
            if ((unsigned)z >= 9u) continue;
#pragma unroll
            for (int yin = 0; yin < 5; yin++) {
                const int y = 2 * py - 1 + yin;
                if ((unsigned)y >= 9u) continue;
                const float* row = xp + ((size_t)z * 9 + y) * 9;
                float in[5];
#pragma unroll
                for (int xi = 0; xi < 5; xi++) {
                    const int xx = 2 * px - 1 + xi;
                    in[xi] = ((unsigned)xx < 9u) ? __ldg(row + xx) : 0.0f;
                }
#pragma unroll
                for (int oz = 0; oz < 2; oz++) {
                    const int kz = zin - oz;
                    if (kz < 0 || kz > 3) continue;
#pragma unroll
                    for (int oy = 0; oy < 2; oy++) {
                        const int ky = yin - oy;
                        if (ky < 0 || ky > 3) continue;
                        const float* wr = wc + (kz * 4 + ky) * 4;
#pragma unroll
                        for (int kx = 0; kx < 4; kx++) {
                            const float wv = wr[kx];
                            acc[oz][oy][0] = fmaf(wv, in[kx], acc[oz][oy][0]);
                            acc[oz][oy][1] = fmaf(wv, in[kx + 1], acc[oz][oy][1]);
                        }
                    }
                }
            }
        }
    }
    float m = -CUDART_INF_F;
#pragma unroll
    for (int oz = 0; oz < 2; oz++)
#pragma unroll
        for (int oy = 0; oy < 2; oy++)
#pragma unroll
            for (int ox = 0; ox < 2; ox++)
                m = fmaxf(m, acc[oz][oy][ox] + sb);
    const float v = (m >= 0.0f) ? m : sa * m;
    out[(((size_t)(n * 64 + c) * 4 + pz) * 4 + py) * 4 + px] = v;
}

// ---------------- conv3: 64->64, k3, pad0, + reshape to feat ----------------
// grid (80), block (512)
__global__ void conv3_kernel(const float* __restrict__ x,
                             const float* __restrict__ w,
                             const float* __restrict__ bias,
                             const float* __restrict__ prelu,
                             float* __restrict__ feat) {
    const int n = blockIdx.x;
    const int tid = threadIdx.x;
    __shared__ float sin[64 * 64];  // [ic][z*16+y*4+x]
    for (int i = tid; i < 4096; i += 512) sin[i] = x[(size_t)n * 4096 + i];
    __syncthreads();

    const int c = tid >> 3, s = tid & 7;
    const int oz = s >> 2, oy = (s >> 1) & 1, ox = s & 1;
    float acc = bias[c];
    const float* wc = w + (size_t)c * 64 * 27;
    for (int ic = 0; ic < 64; ic++) {
        const float* si = sin + ic * 64;
        const float* wi = wc + ic * 27;
#pragma unroll
        for (int kz = 0; kz < 3; kz++)
#pragma unroll
            for (int ky = 0; ky < 3; ky++)
#pragma unroll
                for (int kx = 0; kx < 3; kx++)
                    acc = fmaf(__ldg(wi + (kz * 3 + ky) * 3 + kx),
                               si[(oz + kz) * 16 + (oy + ky) * 4 + (ox + kx)], acc);
    }
    const float a = prelu[0];
    const float v = (acc >= 0.0f) ? acc : a * acc;
    feat[(size_t)n * 512 + c * 8 + s] = v;
}

// ---------------- mean over agents ----------------
// grid (16), block (D)
__global__ void mean_kernel(const float* __restrict__ feat, float* __restrict__ mean, int D) {
    const int b = blockIdx.x, i = threadIdx.x;
    float s = 0.0f;
    for (int a = 0; a < 5; a++) s += feat[((size_t)(b * 5 + a)) * D + i];
    mean[(size_t)b * D + i] = s * (1.0f / 5.0f);
}

// ---------------- comm fc (+optional prelu) ----------------
// grid (80), block (O). out[b,a,o] = b[a,o] + sum_i feat[b,a,i]*w[a,o,i] + mean[b,i]*w[a,o,D+i]
__global__ void commfc_kernel(const float* __restrict__ feat,
                              const float* __restrict__ mean,
                              const float* __restrict__ w,
                              const float* __restrict__ bias,
                              const float* __restrict__ prelu,  // nullptr => no activation
                              float* __restrict__ out, int D, int O) {
    const int bx = blockIdx.x;
    const int b = bx / 5, a = bx % 5;
    const int o = threadIdx.x;
    if (o >= O) return;
    const float* fp = feat + (size_t)bx * D;
    const float* mp = mean + (size_t)b * D;
    const float* wp = w + ((size_t)a * O + o) * (2 * D);
    float acc = bias[a * O + o];
    for (int i = 0; i < D; i++) {
        acc = fmaf(fp[i], __ldg(wp + i), acc);
        acc = fmaf(mp[i], __ldg(wp + D + i), acc);
    }
    if (prelu) {
        const float al = prelu[0];
        acc = (acc >= 0.0f) ? acc : al * acc;
    }
    out[(size_t)bx * O + o] = acc;
}

extern "C" void kernel_launch(void* const* d_in, const int* in_sizes, int n_in,
                              void* d_out, int out_size) {
    const float* x        = (const float*)d_in[0];
    const float* conv0_w  = (const float*)d_in[1];
    const float* conv0_b  = (const float*)d_in[2];
    const float* prelu0   = (const float*)d_in[3];
    const float* conv1_w  = (const float*)d_in[4];
    const float* conv1_b  = (const float*)d_in[5];
    const float* prelu1   = (const float*)d_in[6];
    const float* conv2_w  = (const float*)d_in[7];
    const float* conv2_b  = (const float*)d_in[8];
    const float* prelu2   = (const float*)d_in[9];
    const float* conv3_w  = (const float*)d_in[10];
    const float* conv3_b  = (const float*)d_in[11];
    const float* prelu3   = (const float*)d_in[12];
    const float* fc1_w    = (const float*)d_in[13];
    const float* fc1_b    = (const float*)d_in[14];
    const float* prelu4   = (const float*)d_in[15];
    const float* fc2_w    = (const float*)d_in[16];
    const float* fc2_b    = (const float*)d_in[17];
    const float* prelu5   = (const float*)d_in[18];
    const float* fc3_w    = (const float*)d_in[19];
    const float* fc3_b    = (const float*)d_in[20];
    float* out = (float*)d_out;

    float *buf0, *buf1, *buf2, *feat, *mean1, *fc1, *mean2, *fc2, *mean3;
    cudaGetSymbolAddress((void**)&buf0,  g_buf0);
    cudaGetSymbolAddress((void**)&buf1,  g_buf1);
    cudaGetSymbolAddress((void**)&buf2,  g_buf2);
    cudaGetSymbolAddress((void**)&feat,  g_feat);
    cudaGetSymbolAddress((void**)&mean1, g_mean1);
    cudaGetSymbolAddress((void**)&fc1,   g_fc1);
    cudaGetSymbolAddress((void**)&mean2, g_mean2);
    cudaGetSymbolAddress((void**)&fc2,   g_fc2);
    cudaGetSymbolAddress((void**)&mean3, g_mean3);

    conv0_kernel<<<dim3(21, 32, NN), dim3(21, 21)>>>(x, conv0_w, conv0_b, prelu0, buf0);
    conv1_kernel<<<dim3(3, 32, NN), dim3(9, 9, 3)>>>(buf0, conv1_w, conv1_b, prelu1, buf1);
    conv2_kernel<<<dim3(64, NN), dim3(4, 4, 4)>>>(buf1, conv2_w, conv2_b, prelu2, buf2);
    conv3_kernel<<<NN, 512>>>(buf2, conv3_w, conv3_b, prelu3, feat);

    mean_kernel<<<16, 512>>>(feat, mean1, 512);
    commfc_kernel<<<NN, 256>>>(feat, mean1, fc1_w, fc1_b, prelu4, fc1, 512, 256);
    mean_kernel<<<16, 256>>>(fc1, mean2, 256);
    commfc_kernel<<<NN, 128>>>(fc1, mean2, fc2_w, fc2_b, prelu5, fc2, 256, 128);
    mean_kernel<<<16, 128>>>(fc2, mean3, 128);
    commfc_kernel<<<NN, 32>>>(fc2, mean3, fc3_w, fc3_b, nullptr, out, 128, 6);
}

// round 2
// speedup vs baseline: 1.9340x; 1.9340x over previous
#include <cuda_runtime.h>
#include <cuda_bf16.h>
#include <math_constants.h>

// ---------------- shapes ----------------
// B=16, A=5 -> N = 80 folded batch
// x: [80, 4, 45,45,45]
// conv0: 4->32 k5 p1 : 45 -> 43 -> pool 21
// conv1: 32->32 k5 p1: 21 -> 19 -> pool 9
// conv2: 32->64 k4 p1: 9  -> 8  -> pool 4
// conv3: 64->64 k3 p0: 4  -> 2          -> feat [80,512]
// fc1: 1024->256, fc2: 512->128, fc3: 256->6 (per-agent, mean-comm concat)

#define NN 80

typedef unsigned long long ull;

__device__ __forceinline__ ull pack2(float lo, float hi) {
    ull r; asm("mov.b64 %0, {%1, %2};" : "=l"(r) : "f"(lo), "f"(hi)); return r;
}
__device__ __forceinline__ void fma2(ull& d, ull a, ull b) {
    asm("fma.rn.f32x2 %0, %1, %2, %0;" : "+l"(d) : "l"(a), "l"(b));
}
__device__ __forceinline__ float2 unpack2(ull v) {
    float2 f; asm("mov.b64 {%0, %1}, %2;" : "=f"(f.x), "=f"(f.y) : "l"(v)); return f;
}

__device__ float g_buf0[80u * 32u * 21u * 21u * 21u];   // 94.8 MB
__device__ float g_buf1[80u * 32u * 9u * 9u * 9u];
__device__ float g_buf2[80u * 64u * 4u * 4u * 4u];
__device__ float g_feat[80u * 512u];
__device__ float g_mean1[16u * 512u];
__device__ float g_fc1[80u * 256u];
__device__ float g_mean2[16u * 256u];
__device__ float g_fc2[80u * 128u];
__device__ float g_mean3[16u * 128u];

// ---------------- conv0: 4->32, k5, pad1, fused pool2, f32x2 ----------------
// grid (21 pz, 16 cpair, 80 n), block (7 tx, 21 py)
// Thread: 3 pooled-x (px = 3*tx + pxl), 2 output channels, 2x2x2 pool window.
__global__ void conv0_kernel(const float* __restrict__ x,
                             const float* __restrict__ w,
                             const float* __restrict__ bias,
                             const float* __restrict__ prelu,
                             float* __restrict__ out) {
    const int pz = blockIdx.x, cg = blockIdx.y, n = blockIdx.z;
    const int tx = threadIdx.x, py = threadIdx.y;
    __shared__ __align__(16) float ws[2 * 4 * 5 * 5 * 8];  // padded kx->8
    __shared__ float sb[2];
    __shared__ float sa;
    const int tid = py * 7 + tx;
    for (int i = tid; i < 1000; i += 147) {
        int c2 = i / 500, r = i % 500;
        int ic = r / 125, rr = r % 125;
        int kz = rr / 25, ky = (rr / 5) % 5, kx = rr % 5;
        ws[(((c2 * 4 + ic) * 5 + kz) * 5 + ky) * 8 + kx] =
            w[(cg * 2 + c2) * 500 + r] * (1.0f / 255.0f);
    }
    if (tid < 2) sb[tid] = bias[cg * 2 + tid];
    if (tid == 2) {}
    if (tid == 0) sa = prelu[0];
    __syncthreads();

    ull acc[2][3][2][2] = {};  // [c2][pxl][oz][oy], f32x2 over ox
    const int xb = 6 * tx - 1;

    for (int ic = 0; ic < 4; ic++) {
        const float* xp = x + ((size_t)(n * 4 + ic)) * (45 * 45 * 45);
        for (int zin = 0; zin < 6; zin++) {
            const int z = 2 * pz - 1 + zin;
            if ((unsigned)z >= 45u) continue;
            const bool oz0 = (zin <= 4), oz1 = (zin >= 1);
            for (int yin = 0; yin < 6; yin++) {
                const int y = 2 * py - 1 + yin;
                if ((unsigned)y >= 45u) continue;
                const float* row = xp + (z * 45 + y) * 45;
                float in[10];
#pragma unroll
                for (int i = 0; i < 10; i++) {
                    const int xx = xb + i;
                    in[i] = ((unsigned)xx < 45u) ? __ldg(row + xx) : 0.0f;
                }
                ull p[9];
#pragma unroll
                for (int i = 0; i < 9; i++) p[i] = pack2(in[i], in[i + 1]);
                const bool oy0 = (yin <= 4), oy1 = (yin >= 1);
#pragma unroll
                for (int oz = 0; oz < 2; oz++) {
                    if (oz ? !oz1 : !oz0) continue;
                    const int kz = zin - oz;
#pragma unroll
                    for (int oy = 0; oy < 2; oy++) {
                        if (oy ? !oy1 : !oy0) continue;
                        const int ky = yin - oy;
#pragma unroll
                        for (int c2 = 0; c2 < 2; c2++) {
                            const float* wr = &ws[(((c2 * 4 + ic) * 5 + kz) * 5 + ky) * 8];
                            const float4 w4 = *(const float4*)wr;
                            const float w5 = wr[4];
                            const ull W0 = pack2(w4.x, w4.x), W1 = pack2(w4.y, w4.y),
                                      W2 = pack2(w4.z, w4.z), W3 = pack2(w4.w, w4.w),
                                      W4 = pack2(w5, w5);
#pragma unroll
                            for (int pxl = 0; pxl < 3; pxl++) {
                                ull& A = acc[c2][pxl][oz][oy];
                                fma2(A, W0, p[2 * pxl + 0]);
                                fma2(A, W1, p[2 * pxl + 1]);
                                fma2(A, W2, p[2 * pxl + 2]);
                                fma2(A, W3, p[2 * pxl + 3]);
                                fma2(A, W4, p[2 * pxl + 4]);
                            }
                        }
                    }
                }
            }
        }
    }
#pragma unroll
    for (int c2 = 0; c2 < 2; c2++) {
        const float b = sb[c2];
#pragma unroll
        for (int pxl = 0; pxl < 3; pxl++) {
            float m = -CUDART_INF_F;
#pragma unroll
            for (int oz = 0; oz < 2; oz++)
#pragma unroll
                for (int oy = 0; oy < 2; oy++) {
                    const float2 v = unpack2(acc[c2][pxl][oz][oy]);
                    m = fmaxf(m, fmaxf(v.x, v.y));
                }
            m += b;
            const float v = (m >= 0.0f) ? m : sa * m;
            out[(((size_t)(n * 32 + cg * 2 + c2) * 21 + pz) * 21 + py) * 21 + 3 * tx + pxl] = v;
        }
    }
}

// ---------------- conv1: 32->32, k5, pad1, fused pool2, f32x2 ----------------
// grid (16 cpair, 80 n), block (3 tx, 9 py, 9 pz)
__global__ void conv1_kernel(const float* __restrict__ x,
                             const float* __restrict__ w,
                             const float* __restrict__ bias,
                             const float* __restrict__ prelu,
                             float* __restrict__ out) {
    const int cg = blockIdx.x, n = blockIdx.y;
    const int tx = threadIdx.x, py = threadIdx.y, pz = threadIdx.z;
    __shared__ __align__(16) float ws[2 * 32 * 5 * 5 * 6];  // padded kx->6, 38.4KB
    __shared__ float sb[2];
    __shared__ float sa;
    const int tid = (pz * 9 + py) * 3 + tx;
    for (int i = tid; i < 8000; i += 243) {
        int c2 = i / 4000, r = i % 4000;
        int ic = r / 125, rr = r % 125;
        int kz = rr / 25, ky = (rr / 5) % 5, kx = rr % 5;
        ws[(((c2 * 32 + ic) * 5 + kz) * 5 + ky) * 6 + kx] = w[(cg * 2 + c2) * 4000 + r];
    }
    if (tid < 2) sb[tid] = bias[cg * 2 + tid];
    if (tid == 0) sa = prelu[0];
    __syncthreads();

    ull acc[2][3][2][2] = {};
    const int xb = 6 * tx - 1;

    for (int ic = 0; ic < 32; ic++) {
        const float* xp = x + ((size_t)(n * 32 + ic)) * (21 * 21 * 21);
        for (int zin = 0; zin < 6; zin++) {
            const int z = 2 * pz - 1 + zin;
            if ((unsigned)z >= 21u) continue;
            const bool oz0 = (zin <= 4), oz1 = (zin >= 1);
            for (int yin = 0; yin < 6; yin++) {
                const int y = 2 * py - 1 + yin;
                if ((unsigned)y >= 21u) continue;
                const float* row = xp + (z * 21 + y) * 21;
                float in[10];
#pragma unroll
                for (int i = 0; i < 10; i++) {
                    const int xx = xb + i;
                    in[i] = ((unsigned)xx < 21u) ? __ldg(row + xx) : 0.0f;
                }
                ull p[9];
#pragma unroll
                for (int i = 0; i < 9; i++) p[i] = pack2(in[i], in[i + 1]);
                const bool oy0 = (yin <= 4), oy1 = (yin >= 1);
#pragma unroll
                for (int oz = 0; oz < 2; oz++) {
                    if (oz ? !oz1 : !oz0) continue;
                    const int kz = zin - oz;
#pragma unroll
                    for (int oy = 0; oy < 2; oy++) {
                        if (oy ? !oy1 : !oy0) continue;
                        const int ky = yin - oy;
#pragma unroll
                        for (int c2 = 0; c2 < 2; c2++) {
                            const float* wr = &ws[(((c2 * 32 + ic) * 5 + kz) * 5 + ky) * 6];
                            const float2 wa = *(const float2*)wr;
                            const float2 wb = *(const float2*)(wr + 2);
                            const float w4 = wr[4];
                            const ull W0 = pack2(wa.x, wa.x), W1 = pack2(wa.y, wa.y),
                                      W2 = pack2(wb.x, wb.x), W3 = pack2(wb.y, wb.y),
                                      W4 = pack2(w4, w4);
#pragma unroll
                            for (int pxl = 0; pxl < 3; pxl++) {
                                ull& A = acc[c2][pxl][oz][oy];
                                fma2(A, W0, p[2 * pxl + 0]);
                                fma2(A, W1, p[2 * pxl + 1]);
                                fma2(A, W2, p[2 * pxl + 2]);
                                fma2(A, W3, p[2 * pxl + 3]);
                                fma2(A, W4, p[2 * pxl + 4]);
                            }
                        }
                    }
                }
            }
        }
    }
#pragma unroll
    for (int c2 = 0; c2 < 2; c2++) {
        const float b = sb[c2];
#pragma unroll
        for (int pxl = 0; pxl < 3; pxl++) {
            float m = -CUDART_INF_F;
#pragma unroll
            for (int oz = 0; oz < 2; oz++)
#pragma unroll
                for (int oy = 0; oy < 2; oy++) {
                    const float2 v = unpack2(acc[c2][pxl][oz][oy]);
                    m = fmaxf(m, fmaxf(v.x, v.y));
                }
            m += b;
            const float v = (m >= 0.0f) ? m : sa * m;
            out[(((size_t)(n * 32 + cg * 2 + c2) * 9 + pz) * 9 + py) * 9 + 3 * tx + pxl] = v;
        }
    }
}

// ---------------- conv2: 32->64, k4, pad1, fused pool2, f32x2 ----------------
// grid (16 cgroup, 80 n), block (4 py, 4 pz, 4 c4); thread: all 4 px, 1 channel
__global__ void conv2_kernel(const float* __restrict__ x,
                             const float* __restrict__ w,
                             const float* __restrict__ bias,
                             const float* __restrict__ prelu,
                             float* __restrict__ out) {
    const int bx = blockIdx.x, n = blockIdx.y;
    const int py = threadIdx.x, pz = threadIdx.y, c4 = threadIdx.z;
    __shared__ __align__(16) float ws[4 * 2048];  // [c4][ic][kz][ky][kx], 32KB
    __shared__ float sb[4];
    __shared__ float sa;
    const int tid = (c4 * 4 + pz) * 4 + py;
    for (int i = tid; i < 8192; i += 64) ws[i] = w[(size_t)bx * 8192 + i];
    if (tid < 4) sb[tid] = bias[bx * 4 + tid];
    if (tid == 0) sa = prelu[0];
    __syncthreads();

    ull acc[4][2][2] = {};  // [px][oz][oy], f32x2 over ox

    for (int ic = 0; ic < 32; ic++) {
        const float* xp = x + ((size_t)(n * 32 + ic)) * (9 * 9 * 9);
#pragma unroll
        for (int zin = 0; zin < 5; zin++) {
            const int z = 2 * pz - 1 + zin;
            if ((unsigned)z >= 9u) continue;
            const bool oz0 = (zin <= 3), oz1 = (zin >= 1);
#pragma unroll
            for (int yin = 0; yin < 5; yin++) {
                const int y = 2 * py - 1 + yin;
                if ((unsigned)y >= 9u) continue;
                const float* row = xp + (z * 9 + y) * 9;
                float in[11];
#pragma unroll
                for (int i = 0; i < 11; i++) {
                    const int xx = i - 1;
                    in[i] = ((unsigned)xx < 9u) ? __ldg(row + xx) : 0.0f;
                }
                ull p[10];
#pragma unroll
                for (int i = 0; i < 10; i++) p[i] = pack2(in[i], in[i + 1]);
                const bool oy0 = (yin <= 3), oy1 = (yin >= 1);
#pragma unroll
                for (int oz = 0; oz < 2; oz++) {
                    if (oz ? !oz1 : !oz0) continue;
                    const int kz = zin - oz;
#pragma unroll
                    for (int oy = 0; oy < 2; oy++) {
                        if (oy ? !oy1 : !oy0) continue;
                        const int ky = yin - oy;
                        const float* wr = &ws[((c4 * 32 + ic) * 16 + kz * 4 + ky) * 4];
                        const float4 w4 = *(const float4*)wr;
                        const ull W0 = pack2(w4.x, w4.x), W1 = pack2(w4.y, w4.y),
                                  W2 = pack2(w4.z, w4.z), W3 = pack2(w4.w, w4.w);
#pragma unroll
                        for (int px = 0; px < 4; px++) {
                            ull& A = acc[px][oz][oy];
                            fma2(A, W0, p[2 * px + 0]);
                            fma2(A, W1, p[2 * px + 1]);
                            fma2(A, W2, p[2 * px + 2]);
                            fma2(A, W3, p[2 * px + 3]);
                        }
                    }
                }
            }
        }
    }
    const float b = sb[c4];
#pragma unroll
    for (int px = 0; px < 4; px++) {
        float m = -CUDART_INF_F;
#pragma unroll
        for (int oz = 0; oz < 2; oz++)
#pragma unroll
            for (int oy = 0; oy < 2; oy++) {
                const float2 v = unpack2(acc[px][oz][oy]);
                m = fmaxf(m, fmaxf(v.x, v.y));
            }
        m += b;
        const float v = (m >= 0.0f) ? m : sa * m;
        out[(((size_t)(n * 64 + bx * 4 + c4) * 4 + pz) * 4 + py) * 4 + px] = v;
    }
}

// ---------------- conv3: 64->64, k3, pad0, + reshape to feat ----------------
// grid (80), block (512)
__global__ void conv3_kernel(const float* __restrict__ x,
                             const float* __restrict__ w,
                             const float* __restrict__ bias,
                             const float* __restrict__ prelu,
                             float* __restrict__ feat) {
    const int n = blockIdx.x;
    const int tid = threadIdx.x;
    __shared__ float sin[64 * 64];  // [ic][z*16+y*4+x]
    for (int i = tid; i < 4096; i += 512) sin[i] = x[(size_t)n * 4096 + i];
    __syncthreads();

    const int c = tid >> 3, s = tid & 7;
    const int oz = s >> 2, oy = (s >> 1) & 1, ox = s & 1;
    float acc = bias[c];
    const float* wc = w + (size_t)c * 64 * 27;
    for (int ic = 0; ic < 64; ic++) {
        const float* si = sin + ic * 64;
        const float* wi = wc + ic * 27;
#pragma unroll
        for (int kz = 0; kz < 3; kz++)
#pragma unroll
            for (int ky = 0; ky < 3; ky++)
#pragma unroll
                for (int kx = 0; kx < 3; kx++)
                    acc = fmaf(__ldg(wi + (kz * 3 + ky) * 3 + kx),
                               si[(oz + kz) * 16 + (oy + ky) * 4 + (ox + kx)], acc);
    }
    const float a = prelu[0];
    const float v = (acc >= 0.0f) ? acc : a * acc;
    feat[(size_t)n * 512 + c * 8 + s] = v;
}

// ---------------- mean over agents ----------------
__global__ void mean_kernel(const float* __restrict__ feat, float* __restrict__ mean, int D) {
    const int b = blockIdx.x, i = threadIdx.x;
    float s = 0.0f;
    for (int a = 0; a < 5; a++) s += feat[((size_t)(b * 5 + a)) * D + i];
    mean[(size_t)b * D + i] = s * (1.0f / 5.0f);
}

// ---------------- comm fc (+optional prelu) ----------------
__global__ void commfc_kernel(const float* __restrict__ feat,
                              const float* __restrict__ mean,
                              const float* __restrict__ w,
                              const float* __restrict__ bias,
                              const float* __restrict__ prelu,
                              float* __restrict__ out, int D, int O) {
    const int bx = blockIdx.x;
    const int b = bx / 5, a = bx % 5;
    const int o = threadIdx.x;
    if (o >= O) return;
    const float* fp = feat + (size_t)bx * D;
    const float* mp = mean + (size_t)b * D;
    const float* wp = w + ((size_t)a * O + o) * (2 * D);
    float acc = bias[a * O + o];
    for (int i = 0; i < D; i++) {
        acc = fmaf(fp[i], __ldg(wp + i), acc);
        acc = fmaf(mp[i], __ldg(wp + D + i), acc);
    }
    if (prelu) {
        const float al = prelu[0];
        acc = (acc >= 0.0f) ? acc : al * acc;
    }
    out[(size_t)bx * O + o] = acc;
}

extern "C" void kernel_launch(void* const* d_in, const int* in_sizes, int n_in,
                              void* d_out, int out_size) {
    const float* x        = (const float*)d_in[0];
    const float* conv0_w  = (const float*)d_in[1];
    const float* conv0_b  = (const float*)d_in[2];
    const float* prelu0   = (const float*)d_in[3];
    const float* conv1_w  = (const float*)d_in[4];
    const float* conv1_b  = (const float*)d_in[5];
    const float* prelu1   = (const float*)d_in[6];
    const float* conv2_w  = (const float*)d_in[7];
    const float* conv2_b  = (const float*)d_in[8];
    const float* prelu2   = (const float*)d_in[9];
    const float* conv3_w  = (const float*)d_in[10];
    const float* conv3_b  = (const float*)d_in[11];
    const float* prelu3   = (const float*)d_in[12];
    const float* fc1_w    = (const float*)d_in[13];
    const float* fc1_b    = (const float*)d_in[14];
    const float* prelu4   = (const float*)d_in[15];
    const float* fc2_w    = (const float*)d_in[16];
    const float* fc2_b    = (const float*)d_in[17];
    const float* prelu5   = (const float*)d_in[18];
    const float* fc3_w    = (const float*)d_in[19];
    const float* fc3_b    = (const float*)d_in[20];
    float* out = (float*)d_out;

    float *buf0, *buf1, *buf2, *feat, *mean1, *fc1, *mean2, *fc2, *mean3;
    cudaGetSymbolAddress((void**)&buf0,  g_buf0);
    cudaGetSymbolAddress((void**)&buf1,  g_buf1);
    cudaGetSymbolAddress((void**)&buf2,  g_buf2);
    cudaGetSymbolAddress((void**)&feat,  g_feat);
    cudaGetSymbolAddress((void**)&mean1, g_mean1);
    cudaGetSymbolAddress((void**)&fc1,   g_fc1);
    cudaGetSymbolAddress((void**)&mean2, g_mean2);
    cudaGetSymbolAddress((void**)&fc2,   g_fc2);
    cudaGetSymbolAddress((void**)&mean3, g_mean3);

    conv0_kernel<<<dim3(21, 16, NN), dim3(7, 21)>>>(x, conv0_w, conv0_b, prelu0, buf0);
    conv1_kernel<<<dim3(16, NN), dim3(3, 9, 9)>>>(buf0, conv1_w, conv1_b, prelu1, buf1);
    conv2_kernel<<<dim3(16, NN), dim3(4, 4, 4)>>>(buf1, conv2_w, conv2_b, prelu2, buf2);
    conv3_kernel<<<NN, 512>>>(buf2, conv3_w, conv3_b, prelu3, feat);

    mean_kernel<<<16, 512>>>(feat, mean1, 512);
    commfc_kernel<<<NN, 256>>>(feat, mean1, fc1_w, fc1_b, prelu4, fc1, 512, 256);
    mean_kernel<<<16, 256>>>(fc1, mean2, 256);
    commfc_kernel<<<NN, 128>>>(fc1, mean2, fc2_w, fc2_b, prelu5, fc2, 256, 128);
    mean_kernel<<<16, 128>>>(fc2, mean3, 128);
    commfc_kernel<<<NN, 32>>>(fc2, mean3, fc3_w, fc3_b, nullptr, out, 128, 6);
}

// round 6
// speedup vs baseline: 2.4175x; 1.2500x over previous
#include <cuda_runtime.h>
#include <cuda_bf16.h>
#include <math_constants.h>

// ---------------- shapes ----------------
// B=16, A=5 -> N = 80 folded batch
// x: [80, 4, 45,45,45]
// conv0: 4->32 k5 p1 : 45 -> 43 -> pool 21
// conv1: 32->32 k5 p1: 21 -> 19 -> pool 9
// conv2: 32->64 k4 p1: 9  -> 8  -> pool 4
// conv3: 64->64 k3 p0: 4  -> 2          -> feat [80,512]
// fc1: 1024->256, fc2: 512->128, fc3: 256->6 (per-agent, mean-comm concat)

#define NN 80

typedef unsigned long long ull;

__device__ __forceinline__ ull pack2(float lo, float hi) {
    ull r; asm("mov.b64 %0, {%1, %2};" : "=l"(r) : "f"(lo), "f"(hi)); return r;
}
__device__ __forceinline__ void fma2(ull& d, ull a, ull b) {
    asm("fma.rn.f32x2 %0, %1, %2, %0;" : "+l"(d) : "l"(a), "l"(b));
}
__device__ __forceinline__ float2 unpack2(ull v) {
    float2 f; asm("mov.b64 {%0, %1}, %2;" : "=f"(f.x), "=f"(f.y) : "l"(v)); return f;
}

__device__ float g_buf0[80u * 32u * 21u * 21u * 21u];   // 94.8 MB
__device__ float g_buf1[80u * 32u * 9u * 9u * 9u];
__device__ float g_buf2[80u * 64u * 4u * 4u * 4u];
__device__ float g_feat[80u * 512u];
__device__ float g_mean1[16u * 512u];
__device__ float g_fc1[80u * 256u];
__device__ float g_mean2[16u * 256u];
__device__ float g_fc2[80u * 128u];
__device__ float g_mean3[16u * 128u];

// ---------------- conv0: 4->32, k5, pad1, fused pool2 ----------------
// f32x2 over CHANNEL PAIR. grid (21 pz, 16 cg, 80 n), block (7 tx, 21 py)
// Thread: 3 pooled-x, channel pair (cg*2, cg*2+1), full 2x2x2 pool window.
__global__ void conv0_kernel(const float* __restrict__ x,
                             const float* __restrict__ w,
                             const float* __restrict__ bias,
                             const float* __restrict__ prelu,
                             float* __restrict__ out) {
    const int pz = blockIdx.x, cg = blockIdx.y, n = blockIdx.z;
    const int tx = threadIdx.x, py = threadIdx.y;
    // [ic][kz][ky][kx padded 5->6] of (w_c0, w_c1) pairs; 48B row stride (16B aligned)
    __shared__ __align__(16) ull ws[4 * 5 * 5 * 6];
    __shared__ float sb[2];
    __shared__ float sa;
    const int tid = py * 7 + tx;
    for (int i = tid; i < 500; i += 147) {
        const int ic = i / 125, rr = i % 125;
        const int kz = rr / 25, ky = (rr / 5) % 5, kx = rr % 5;
        const float w0 = w[(cg * 2 + 0) * 500 + i] * (1.0f / 255.0f);
        const float w1 = w[(cg * 2 + 1) * 500 + i] * (1.0f / 255.0f);
        ws[((ic * 5 + kz) * 5 + ky) * 6 + kx] = pack2(w0, w1);
    }
    if (tid < 2) sb[tid] = bias[cg * 2 + tid];
    if (tid == 0) sa = prelu[0];
    __syncthreads();

    ull acc[3][2][2][2] = {};  // [pxl][ox][oz][oy], f32x2 over channel pair
    const int xb = 6 * tx - 1;

    for (int ic = 0; ic < 4; ic++) {
        const float* xp = x + ((size_t)(n * 4 + ic)) * (45 * 45 * 45);
        for (int zin = 0; zin < 6; zin++) {
            const int z = 2 * pz - 1 + zin;
            if ((unsigned)z >= 45u) continue;
            const bool oz0 = (zin <= 4), oz1 = (zin >= 1);
            for (int yin = 0; yin < 6; yin++) {
                const int y = 2 * py - 1 + yin;
                if ((unsigned)y >= 45u) continue;
                const float* row = xp + (z * 45 + y) * 45;
                float in[10];
#pragma unroll
                for (int i = 0; i < 10; i++) {
                    const int xx = xb + i;
                    in[i] = ((unsigned)xx < 45u) ? __ldg(row + xx) : 0.0f;
                }
                ull p[10];
#pragma unroll
                for (int i = 0; i < 10; i++) p[i] = pack2(in[i], in[i]);
                const bool oy0 = (yin <= 4), oy1 = (yin >= 1);
#pragma unroll
                for (int oz = 0; oz < 2; oz++) {
                    if (oz ? !oz1 : !oz0) continue;
                    const int kz = zin - oz;
#pragma unroll
                    for (int oy = 0; oy < 2; oy++) {
                        if (oy ? !oy1 : !oy0) continue;
                        const int ky = yin - oy;
                        const ull* wr = &ws[((ic * 5 + kz) * 5 + ky) * 6];
                        const ulonglong2 wab = *(const ulonglong2*)wr;
                        const ulonglong2 wcd = *(const ulonglong2*)(wr + 2);
                        const ull W4 = wr[4];
#pragma unroll
                        for (int pxl = 0; pxl < 3; pxl++) {
#pragma unroll
                            for (int ox = 0; ox < 2; ox++) {
                                ull& A = acc[pxl][ox][oz][oy];
                                const int b = 2 * pxl + ox;
                                fma2(A, wab.x, p[b + 0]);
                                fma2(A, wab.y, p[b + 1]);
                                fma2(A, wcd.x, p[b + 2]);
                                fma2(A, wcd.y, p[b + 3]);
                                fma2(A, W4,    p[b + 4]);
                            }
                        }
                    }
                }
            }
        }
    }
#pragma unroll
    for (int pxl = 0; pxl < 3; pxl++) {
        float m0 = -CUDART_INF_F, m1 = -CUDART_INF_F;
#pragma unroll
        for (int ox = 0; ox < 2; ox++)
#pragma unroll
            for (int oz = 0; oz < 2; oz++)
#pragma unroll
                for (int oy = 0; oy < 2; oy++) {
                    const float2 v = unpack2(acc[pxl][ox][oz][oy]);
                    m0 = fmaxf(m0, v.x);
                    m1 = fmaxf(m1, v.y);
                }
        m0 += sb[0]; m1 += sb[1];
        const float v0 = (m0 >= 0.0f) ? m0 : sa * m0;
        const float v1 = (m1 >= 0.0f) ? m1 : sa * m1;
        const int px = 3 * tx + pxl;
        out[(((size_t)(n * 32 + cg * 2 + 0) * 21 + pz) * 21 + py) * 21 + px] = v0;
        out[(((size_t)(n * 32 + cg * 2 + 1) * 21 + pz) * 21 + py) * 21 + px] = v1;
    }
}

// ---------------- conv1: 32->32, k5, pad1, fused pool2 ----------------
// f32x2 over CHANNEL PAIR. grid (16 cg, 80 n), block (3 tx, 9 py, 9 pz)
__global__ void conv1_kernel(const float* __restrict__ x,
                             const float* __restrict__ w,
                             const float* __restrict__ bias,
                             const float* __restrict__ prelu,
                             float* __restrict__ out) {
    const int cg = blockIdx.x, n = blockIdx.y;
    const int tx = threadIdx.x, py = threadIdx.y, pz = threadIdx.z;
    __shared__ __align__(16) ull ws[32 * 5 * 5 * 6];  // 38.4KB, channel pairs
    __shared__ float sb[2];
    __shared__ float sa;
    const int tid = (pz * 9 + py) * 3 + tx;
    for (int i = tid; i < 4000; i += 243) {
        const int ic = i / 125, rr = i % 125;
        const int kz = rr / 25, ky = (rr / 5) % 5, kx = rr % 5;
        const float w0 = w[(cg * 2 + 0) * 4000 + i];
        const float w1 = w[(cg * 2 + 1) * 4000 + i];
        ws[((ic * 5 + kz) * 5 + ky) * 6 + kx] = pack2(w0, w1);
    }
    if (tid < 2) sb[tid] = bias[cg * 2 + tid];
    if (tid == 0) sa = prelu[0];
    __syncthreads();

    ull acc[3][2][2][2] = {};
    const int xb = 6 * tx - 1;

    for (int ic = 0; ic < 32; ic++) {
        const float* xp = x + ((size_t)(n * 32 + ic)) * (21 * 21 * 21);
        for (int zin = 0; zin < 6; zin++) {
            const int z = 2 * pz - 1 + zin;
            if ((unsigned)z >= 21u) continue;
            const bool oz0 = (zin <= 4), oz1 = (zin >= 1);
            for (int yin = 0; yin < 6; yin++) {
                const int y = 2 * py - 1 + yin;
                if ((unsigned)y >= 21u) continue;
                const float* row = xp + (z * 21 + y) * 21;
                float in[10];
#pragma unroll
                for (int i = 0; i < 10; i++) {
                    const int xx = xb + i;
                    in[i] = ((unsigned)xx < 21u) ? __ldg(row + xx) : 0.0f;
                }
                ull p[10];
#pragma unroll
                for (int i = 0; i < 10; i++) p[i] = pack2(in[i], in[i]);
                const bool oy0 = (yin <= 4), oy1 = (yin >= 1);
#pragma unroll
                for (int oz = 0; oz < 2; oz++) {
                    if (oz ? !oz1 : !oz0) continue;
                    const int kz = zin - oz;
#pragma unroll
                    for (int oy = 0; oy < 2; oy++) {
                        if (oy ? !oy1 : !oy0) continue;
                        const int ky = yin - oy;
                        const ull* wr = &ws[((ic * 5 + kz) * 5 + ky) * 6];
                        const ulonglong2 wab = *(const ulonglong2*)wr;
                        const ulonglong2 wcd = *(const ulonglong2*)(wr + 2);
                        const ull W4 = wr[4];
#pragma unroll
                        for (int pxl = 0; pxl < 3; pxl++) {
#pragma unroll
                            for (int ox = 0; ox < 2; ox++) {
                                ull& A = acc[pxl][ox][oz][oy];
                                const int b = 2 * pxl + ox;
                                fma2(A, wab.x, p[b + 0]);
                                fma2(A, wab.y, p[b + 1]);
                                fma2(A, wcd.x, p[b + 2]);
                                fma2(A, wcd.y, p[b + 3]);
                                fma2(A, W4,    p[b + 4]);
                            }
                        }
                    }
                }
            }
        }
    }
#pragma unroll
    for (int pxl = 0; pxl < 3; pxl++) {
        float m0 = -CUDART_INF_F, m1 = -CUDART_INF_F;
#pragma unroll
        for (int ox = 0; ox < 2; ox++)
#pragma unroll
            for (int oz = 0; oz < 2; oz++)
#pragma unroll
                for (int oy = 0; oy < 2; oy++) {
                    const float2 v = unpack2(acc[pxl][ox][oz][oy]);
                    m0 = fmaxf(m0, v.x);
                    m1 = fmaxf(m1, v.y);
                }
        m0 += sb[0]; m1 += sb[1];
        const float v0 = (m0 >= 0.0f) ? m0 : sa * m0;
        const float v1 = (m1 >= 0.0f) ? m1 : sa * m1;
        const int px = 3 * tx + pxl;
        out[(((size_t)(n * 32 + cg * 2 + 0) * 9 + pz) * 9 + py) * 9 + px] = v0;
        out[(((size_t)(n * 32 + cg * 2 + 1) * 9 + pz) * 9 + py) * 9 + px] = v1;
    }
}

// ---------------- conv2: 32->64, k4, pad1, fused pool2, f32x2 over ox ----------------
// grid (16 cgroup, 80 n), block (4 py, 4 pz, 4 c4)
__global__ void conv2_kernel(const float* __restrict__ x,
                             const float* __restrict__ w,
                             const float* __restrict__ bias,
                             const float* __restrict__ prelu,
                             float* __restrict__ out) {
    const int bx = blockIdx.x, n = blockIdx.y;
    const int py = threadIdx.x, pz = threadIdx.y, c4 = threadIdx.z;
    __shared__ __align__(16) float ws[4 * 2048];  // [c4][ic][kz][ky][kx], 32KB
    __shared__ float sb[4];
    __shared__ float sa;
    const int tid = (c4 * 4 + pz) * 4 + py;
    for (int i = tid; i < 8192; i += 64) ws[i] = w[(size_t)bx * 8192 + i];
    if (tid < 4) sb[tid] = bias[bx * 4 + tid];
    if (tid == 0) sa = prelu[0];
    __syncthreads();

    ull acc[4][2][2] = {};  // [px][oz][oy], f32x2 over ox

    for (int ic = 0; ic < 32; ic++) {
        const float* xp = x + ((size_t)(n * 32 + ic)) * (9 * 9 * 9);
#pragma unroll
        for (int zin = 0; zin < 5; zin++) {
            const int z = 2 * pz - 1 + zin;
            if ((unsigned)z >= 9u) continue;
            const bool oz0 = (zin <= 3), oz1 = (zin >= 1);
#pragma unroll
            for (int yin = 0; yin < 5; yin++) {
                const int y = 2 * py - 1 + yin;
                if ((unsigned)y >= 9u) continue;
                const float* row = xp + (z * 9 + y) * 9;
                float in[11];
#pragma unroll
                for (int i = 0; i < 11; i++) {
                    const int xx = i - 1;
                    in[i] = ((unsigned)xx < 9u) ? __ldg(row + xx) : 0.0f;
                }
                ull p[10];
#pragma unroll
                for (int i = 0; i < 10; i++) p[i] = pack2(in[i], in[i + 1]);
                const bool oy0 = (yin <= 3), oy1 = (yin >= 1);
#pragma unroll
                for (int oz = 0; oz < 2; oz++) {
                    if (oz ? !oz1 : !oz0) continue;
                    const int kz = zin - oz;
#pragma unroll
                    for (int oy = 0; oy < 2; oy++) {
                        if (oy ? !oy1 : !oy0) continue;
                        const int ky = yin - oy;
                        const float* wr = &ws[((c4 * 32 + ic) * 16 + kz * 4 + ky) * 4];
                        const float4 w4 = *(const float4*)wr;
                        const ull W0 = pack2(w4.x, w4.x), W1 = pack2(w4.y, w4.y),
                                  W2 = pack2(w4.z, w4.z), W3 = pack2(w4.w, w4.w);
#pragma unroll
                        for (int px = 0; px < 4; px++) {
                            ull& A = acc[px][oz][oy];
                            fma2(A, W0, p[2 * px + 0]);
                            fma2(A, W1, p[2 * px + 1]);
                            fma2(A, W2, p[2 * px + 2]);
                            fma2(A, W3, p[2 * px + 3]);
                        }
                    }
                }
            }
        }
    }
    const float b = sb[c4];
#pragma unroll
    for (int px = 0; px < 4; px++) {
        float m = -CUDART_INF_F;
#pragma unroll
        for (int oz = 0; oz < 2; oz++)
#pragma unroll
            for (int oy = 0; oy < 2; oy++) {
                const float2 v = unpack2(acc[px][oz][oy]);
                m = fmaxf(m, fmaxf(v.x, v.y));
            }
        m += b;
        const float v = (m >= 0.0f) ? m : sa * m;
        out[(((size_t)(n * 64 + bx * 4 + c4) * 4 + pz) * 4 + py) * 4 + px] = v;
    }
}

// ---------------- conv3: 64->64, k3, pad0, + reshape to feat ----------------
__global__ void conv3_kernel(const float* __restrict__ x,
                             const float* __restrict__ w,
                             const float* __restrict__ bias,
                             const float* __restrict__ prelu,
                             float* __restrict__ feat) {
    const int n = blockIdx.x;
    const int tid = threadIdx.x;
    __shared__ float sin[64 * 64];  // [ic][z*16+y*4+x]
    for (int i = tid; i < 4096; i += 512) sin[i] = x[(size_t)n * 4096 + i];
    __syncthreads();

    const int c = tid >> 3, s = tid & 7;
    const int oz = s >> 2, oy = (s >> 1) & 1, ox = s & 1;
    float acc = bias[c];
    const float* wc = w + (size_t)c * 64 * 27;
    for (int ic = 0; ic < 64; ic++) {
        const float* si = sin + ic * 64;
        const float* wi = wc + ic * 27;
#pragma unroll
        for (int kz = 0; kz < 3; kz++)
#pragma unroll
            for (int ky = 0; ky < 3; ky++)
#pragma unroll
                for (int kx = 0; kx < 3; kx++)
                    acc = fmaf(__ldg(wi + (kz * 3 + ky) * 3 + kx),
                               si[(oz + kz) * 16 + (oy + ky) * 4 + (ox + kx)], acc);
    }
    const float a = prelu[0];
    const float v = (acc >= 0.0f) ? acc : a * acc;
    feat[(size_t)n * 512 + c * 8 + s] = v;
}

// ---------------- mean over agents ----------------
__global__ void mean_kernel(const float* __restrict__ feat, float* __restrict__ mean, int D) {
    const int b = blockIdx.x, i = threadIdx.x;
    float s = 0.0f;
    for (int a = 0; a < 5; a++) s += feat[((size_t)(b * 5 + a)) * D + i];
    mean[(size_t)b * D + i] = s * (1.0f / 5.0f);
}

// ---------------- comm fc (+optional prelu) ----------------
__global__ void commfc_kernel(const float* __restrict__ feat,
                              const float* __restrict__ mean,
                              const float* __restrict__ w,
                              const float* __restrict__ bias,
                              const float* __restrict__ prelu,
                              float* __restrict__ out, int D, int O) {
    const int bx = blockIdx.x;
    const int b = bx / 5, a = bx % 5;
    const int o = threadIdx.x;
    if (o >= O) return;
    const float* fp = feat + (size_t)bx * D;
    const float* mp = mean + (size_t)b * D;
    const float* wp = w + ((size_t)a * O + o) * (2 * D);
    float acc = bias[a * O + o];
    for (int i = 0; i < D; i++) {
        acc = fmaf(fp[i], __ldg(wp + i), acc);
        acc = fmaf(mp[i], __ldg(wp + D + i), acc);
    }
    if (prelu) {
        const float al = prelu[0];
        acc = (acc >= 0.0f) ? acc : al * acc;
    }
    out[(size_t)bx * O + o] = acc;
}

extern "C" void kernel_launch(void* const* d_in, const int* in_sizes, int n_in,
                              void* d_out, int out_size) {
    const float* x        = (const float*)d_in[0];
    const float* conv0_w  = (const float*)d_in[1];
    const float* conv0_b  = (const float*)d_in[2];
    const float* prelu0   = (const float*)d_in[3];
    const float* conv1_w  = (const float*)d_in[4];
    const float* conv1_b  = (const float*)d_in[5];
    const float* prelu1   = (const float*)d_in[6];
    const float* conv2_w  = (const float*)d_in[7];
    const float* conv2_b  = (const float*)d_in[8];
    const float* prelu2   = (const float*)d_in[9];
    const float* conv3_w  = (const float*)d_in[10];
    const float* conv3_b  = (const float*)d_in[11];
    const float* prelu3   = (const float*)d_in[12];
    const float* fc1_w    = (const float*)d_in[13];
    const float* fc1_b    = (const float*)d_in[14];
    const float* prelu4   = (const float*)d_in[15];
    const float* fc2_w    = (const float*)d_in[16];
    const float* fc2_b    = (const float*)d_in[17];
    const float* prelu5   = (const float*)d_in[18];
    const float* fc3_w    = (const float*)d_in[19];
    const float* fc3_b    = (const float*)d_in[20];
    float* out = (float*)d_out;

    float *buf0, *buf1, *buf2, *feat, *mean1, *fc1, *mean2, *fc2, *mean3;
    cudaGetSymbolAddress((void**)&buf0,  g_buf0);
    cudaGetSymbolAddress((void**)&buf1,  g_buf1);
    cudaGetSymbolAddress((void**)&buf2,  g_buf2);
    cudaGetSymbolAddress((void**)&feat,  g_feat);
    cudaGetSymbolAddress((void**)&mean1, g_mean1);
    cudaGetSymbolAddress((void**)&fc1,   g_fc1);
    cudaGetSymbolAddress((void**)&mean2, g_mean2);
    cudaGetSymbolAddress((void**)&fc2,   g_fc2);
    cudaGetSymbolAddress((void**)&mean3, g_mean3);

    conv0_kernel<<<dim3(21, 16, NN), dim3(7, 21)>>>(x, conv0_w, conv0_b, prelu0, buf0);
    conv1_kernel<<<dim3(16, NN), dim3(3, 9, 9)>>>(buf0, conv1_w, conv1_b, prelu1, buf1);
    conv2_kernel<<<dim3(16, NN), dim3(4, 4, 4)>>>(buf1, conv2_w, conv2_b, prelu2, buf2);
    conv3_kernel<<<NN, 512>>>(buf2, conv3_w, conv3_b, prelu3, feat);

    mean_kernel<<<16, 512>>>(feat, mean1, 512);
    commfc_kernel<<<NN, 256>>>(feat, mean1, fc1_w, fc1_b, prelu4, fc1, 512, 256);
    mean_kernel<<<16, 256>>>(fc1, mean2, 256);
    commfc_kernel<<<NN, 128>>>(fc1, mean2, fc2_w, fc2_b, prelu5, fc2, 256, 128);
    mean_kernel<<<16, 128>>>(fc2, mean3, 128);
    commfc_kernel<<<NN, 32>>>(fc2, mean3, fc3_w, fc3_b, nullptr, out, 128, 6);
}